// round 1
// baseline (speedup 1.0000x reference)
#include <cuda_runtime.h>
#include <cuda_bf16.h>
#include <math.h>

// Problem constants
constexpr int Bc = 2;
constexpr int Sc = 2048;
constexpr int Dc = 1024;
constexpr int Hc = 16;
constexpr int HS = 64;           // head size
constexpr int Mrows = Bc * Sc;   // 4096

// ----------------------------------------------------------------------------
// Scratch (static __device__ globals; allocation in kernel_launch is forbidden)
// ----------------------------------------------------------------------------
__device__ float g_qkv[(size_t)Mrows * 3 * Dc];             // (B,S,3D)   50.3 MB
__device__ float g_ctx[(size_t)Mrows * Dc];                 // (B,S,D)    16.8 MB
__device__ float g_rowmax[(size_t)Bc * Hc * Sc];            // per (bh,i)
__device__ float g_rowsum[(size_t)Bc * Hc * Sc];
__device__ float g_attn[(size_t)Bc * Hc * Sc * Sc];         // fallback if attn_w not in d_out

// ----------------------------------------------------------------------------
// Generic C = A(MxK) * W(NxK)^T + bias  (row-major everything)
// 128x128x8 tile, 256 threads, 8x8 per-thread register tile.
// Requires M%128==0, N%128==0, K%8==0 (true for all our shapes).
// ----------------------------------------------------------------------------
__global__ __launch_bounds__(256) void sgemm_bias_kernel(
    const float* __restrict__ A, const float* __restrict__ W,
    const float* __restrict__ bias, float* __restrict__ C,
    int M, int N, int K)
{
    __shared__ float As[8][128];
    __shared__ float Bs[8][128];

    const int tid  = threadIdx.x;
    const int row0 = blockIdx.y * 128;
    const int col0 = blockIdx.x * 128;

    const int lr = tid >> 1;            // 0..127
    const int lc = (tid & 1) * 4;       // 0 or 4
    const int ty = tid >> 4;            // 0..15
    const int tx = tid & 15;            // 0..15

    const float* Ap = A + (size_t)(row0 + lr) * K + lc;
    const float* Wp = W + (size_t)(col0 + lr) * K + lc;

    float acc[8][8];
#pragma unroll
    for (int i = 0; i < 8; ++i)
#pragma unroll
        for (int j = 0; j < 8; ++j) acc[i][j] = 0.f;

    for (int k0 = 0; k0 < K; k0 += 8) {
        float4 av = *(const float4*)(Ap + k0);
        float4 wv = *(const float4*)(Wp + k0);
        As[lc + 0][lr] = av.x; As[lc + 1][lr] = av.y;
        As[lc + 2][lr] = av.z; As[lc + 3][lr] = av.w;
        Bs[lc + 0][lr] = wv.x; Bs[lc + 1][lr] = wv.y;
        Bs[lc + 2][lr] = wv.z; Bs[lc + 3][lr] = wv.w;
        __syncthreads();
#pragma unroll
        for (int k = 0; k < 8; ++k) {
            float4 a0 = *(const float4*)&As[k][ty * 8];
            float4 a1 = *(const float4*)&As[k][ty * 8 + 4];
            float4 b0 = *(const float4*)&Bs[k][tx * 8];
            float4 b1 = *(const float4*)&Bs[k][tx * 8 + 4];
            float a[8] = {a0.x, a0.y, a0.z, a0.w, a1.x, a1.y, a1.z, a1.w};
            float b[8] = {b0.x, b0.y, b0.z, b0.w, b1.x, b1.y, b1.z, b1.w};
#pragma unroll
            for (int i = 0; i < 8; ++i)
#pragma unroll
                for (int j = 0; j < 8; ++j) acc[i][j] += a[i] * b[j];
        }
        __syncthreads();
    }

    float bz[8];
#pragma unroll
    for (int j = 0; j < 8; ++j) bz[j] = bias[col0 + tx * 8 + j];

#pragma unroll
    for (int i = 0; i < 8; ++i) {
        int row = row0 + ty * 8 + i;
        float* Cp = C + (size_t)row * N + col0 + tx * 8;
        float4 r0 = make_float4(acc[i][0] + bz[0], acc[i][1] + bz[1],
                                acc[i][2] + bz[2], acc[i][3] + bz[3]);
        float4 r1 = make_float4(acc[i][4] + bz[4], acc[i][5] + bz[5],
                                acc[i][6] + bz[6], acc[i][7] + bz[7]);
        *(float4*)Cp       = r0;
        *(float4*)(Cp + 4) = r1;
    }
}

// ----------------------------------------------------------------------------
// Scores: per (query-tile of 64, bh) block. Computes raw scaled scores (causal
// masked entries = -inf), writes them to attn buffer, and computes per-row
// running max / sum-of-exp (online softmax stats) -> g_rowmax / g_rowsum.
// Skips fully-masked key tiles (kt > qt).
// ----------------------------------------------------------------------------
__global__ __launch_bounds__(256) void attn_scores_kernel(
    const float* __restrict__ qkv, float* __restrict__ attn,
    float* __restrict__ rowmax, float* __restrict__ rowsum)
{
    __shared__ float QT[64][64];   // [k][i], Q pre-scaled by 1/sqrt(hs)
    __shared__ float KT[64][64];   // [k][j]

    const int qt = blockIdx.x;         // 0..31
    const int bh = blockIdx.y;         // 0..31
    const int b  = bh >> 4;
    const int h  = bh & 15;
    const float scale = 0.125f;        // 1/sqrt(64)

    const float* Qb = qkv + (size_t)b * Sc * (3 * Dc) + h * HS;
    const float* Kb = Qb + Dc;
    float* attn_bh = attn + (size_t)bh * Sc * Sc;

    const int tid = threadIdx.x;
    const int ty  = tid >> 4;
    const int tx  = tid & 15;

    // Load Q tile (scaled), transposed: QT[k][i]
#pragma unroll
    for (int it = 0; it < 4; ++it) {
        int idx = tid + 256 * it;
        int r = idx >> 4;
        int c = (idx & 15) * 4;
        float4 v = *(const float4*)(Qb + (size_t)(qt * 64 + r) * (3 * Dc) + c);
        QT[c + 0][r] = v.x * scale; QT[c + 1][r] = v.y * scale;
        QT[c + 2][r] = v.z * scale; QT[c + 3][r] = v.w * scale;
    }

    float m[4], s[4];
#pragma unroll
    for (int i = 0; i < 4; ++i) { m[i] = -INFINITY; s[i] = 0.f; }

    for (int kt = 0; kt <= qt; ++kt) {
        __syncthreads();   // previous compute done (and QT visible on kt==0)
#pragma unroll
        for (int it = 0; it < 4; ++it) {
            int idx = tid + 256 * it;
            int r = idx >> 4;
            int c = (idx & 15) * 4;
            float4 v = *(const float4*)(Kb + (size_t)(kt * 64 + r) * (3 * Dc) + c);
            KT[c + 0][r] = v.x; KT[c + 1][r] = v.y;
            KT[c + 2][r] = v.z; KT[c + 3][r] = v.w;
        }
        __syncthreads();

        float acc[4][4];
#pragma unroll
        for (int i = 0; i < 4; ++i)
#pragma unroll
            for (int j = 0; j < 4; ++j) acc[i][j] = 0.f;

#pragma unroll
        for (int k = 0; k < 64; ++k) {
            float4 aq = *(const float4*)&QT[k][ty * 4];
            float4 bk = *(const float4*)&KT[k][tx * 4];
            float a[4] = {aq.x, aq.y, aq.z, aq.w};
            float bb[4] = {bk.x, bk.y, bk.z, bk.w};
#pragma unroll
            for (int i = 0; i < 4; ++i)
#pragma unroll
                for (int j = 0; j < 4; ++j) acc[i][j] += a[i] * bb[j];
        }

        if (kt == qt) {  // diagonal tile: apply causal mask
#pragma unroll
            for (int ii = 0; ii < 4; ++ii) {
                int gi = ty * 4 + ii;
#pragma unroll
                for (int jj = 0; jj < 4; ++jj) {
                    int gj = tx * 4 + jj;
                    if (gj > gi) acc[ii][jj] = -INFINITY;
                }
            }
        }

#pragma unroll
        for (int ii = 0; ii < 4; ++ii) {
            float tmax = fmaxf(fmaxf(acc[ii][0], acc[ii][1]),
                               fmaxf(acc[ii][2], acc[ii][3]));
            float nm = fmaxf(m[ii], tmax);
            if (nm != -INFINITY) {
                float add = __expf(acc[ii][0] - nm) + __expf(acc[ii][1] - nm) +
                            __expf(acc[ii][2] - nm) + __expf(acc[ii][3] - nm);
                s[ii] = s[ii] * __expf(m[ii] - nm) + add;
                m[ii] = nm;
            }
            int gi = qt * 64 + ty * 4 + ii;
            float4 st = make_float4(acc[ii][0], acc[ii][1], acc[ii][2], acc[ii][3]);
            *(float4*)(attn_bh + (size_t)gi * Sc + kt * 64 + tx * 4) = st;
        }
    }

    // Reduce (m,s) across the 16 tx-lanes that share each query row
#pragma unroll
    for (int ii = 0; ii < 4; ++ii) {
        float mm = m[ii], ss = s[ii];
#pragma unroll
        for (int off = 8; off > 0; off >>= 1) {
            float mo = __shfl_xor_sync(0xffffffffu, mm, off);
            float so = __shfl_xor_sync(0xffffffffu, ss, off);
            float M2 = fmaxf(mm, mo);
            ss = (M2 == -INFINITY) ? 0.f
                                   : (ss * __expf(mm - M2) + so * __expf(mo - M2));
            mm = M2;
        }
        if (tx == 0) {
            int gi = qt * 64 + ty * 4 + ii;
            rowmax[(size_t)bh * Sc + gi] = mm;
            rowsum[(size_t)bh * Sc + gi] = ss;
        }
    }
}

// ----------------------------------------------------------------------------
// Normalize: attn[bh][i][j] = (j>i) ? 0 : exp(raw - m[bh,i]) / s[bh,i]
// Elementwise float4 pass; also writes the zeros in the masked triangle
// (d_out is poisoned, so every element must be written).
// ----------------------------------------------------------------------------
__global__ __launch_bounds__(256) void softmax_norm_kernel(
    float* __restrict__ attn, const float* __restrict__ rowmax,
    const float* __restrict__ rowsum)
{
    size_t i4 = (size_t)blockIdx.x * blockDim.x + threadIdx.x;
    size_t base = i4 * 4;
    int j = (int)(base & (size_t)(Sc - 1));
    size_t row = base >> 11;               // / 2048 -> bh*S + i
    int i = (int)(row & (size_t)(Sc - 1));

    float4* p = (float4*)attn + i4;
    float4 v = *p;
    float mrow = rowmax[row];
    float inv  = 1.0f / rowsum[row];
    float4 o;
    o.x = (j + 0 > i) ? 0.f : __expf(v.x - mrow) * inv;
    o.y = (j + 1 > i) ? 0.f : __expf(v.y - mrow) * inv;
    o.z = (j + 2 > i) ? 0.f : __expf(v.z - mrow) * inv;
    o.w = (j + 3 > i) ? 0.f : __expf(v.w - mrow) * inv;
    *p = o;
}

// ----------------------------------------------------------------------------
// PV: per (query-tile, bh): ctx(64 x 64) += attn(64 x Sc_causal) @ V(Sc x 64).
// Skips key tiles beyond the causal boundary (their attn entries are 0).
// ----------------------------------------------------------------------------
__global__ __launch_bounds__(256) void attn_pv_kernel(
    const float* __restrict__ attn, const float* __restrict__ qkv,
    float* __restrict__ ctx)
{
    __shared__ float AT[64][64];   // [k][i]  (attn transposed)
    __shared__ float Vs[64][64];   // [k][e]

    const int qt = blockIdx.x;
    const int bh = blockIdx.y;
    const int b  = bh >> 4;
    const int h  = bh & 15;

    const float* Ab = attn + (size_t)bh * Sc * Sc;
    const float* Vb = qkv + (size_t)b * Sc * (3 * Dc) + 2 * Dc + h * HS;

    const int tid = threadIdx.x;
    const int ty  = tid >> 4;
    const int tx  = tid & 15;

    float acc[4][4];
#pragma unroll
    for (int i = 0; i < 4; ++i)
#pragma unroll
        for (int j = 0; j < 4; ++j) acc[i][j] = 0.f;

    for (int kt = 0; kt <= qt; ++kt) {
        __syncthreads();
#pragma unroll
        for (int it = 0; it < 4; ++it) {
            int idx = tid + 256 * it;
            int r = idx >> 4;
            int c = (idx & 15) * 4;
            float4 a = *(const float4*)(Ab + (size_t)(qt * 64 + r) * Sc + kt * 64 + c);
            AT[c + 0][r] = a.x; AT[c + 1][r] = a.y;
            AT[c + 2][r] = a.z; AT[c + 3][r] = a.w;
            float4 v = *(const float4*)(Vb + (size_t)(kt * 64 + r) * (3 * Dc) + c);
            *(float4*)&Vs[r][c] = v;
        }
        __syncthreads();
#pragma unroll
        for (int k = 0; k < 64; ++k) {
            float4 aa = *(const float4*)&AT[k][ty * 4];
            float4 vv = *(const float4*)&Vs[k][tx * 4];
            float a[4] = {aa.x, aa.y, aa.z, aa.w};
            float v[4] = {vv.x, vv.y, vv.z, vv.w};
#pragma unroll
            for (int i = 0; i < 4; ++i)
#pragma unroll
                for (int j = 0; j < 4; ++j) acc[i][j] += a[i] * v[j];
        }
    }

#pragma unroll
    for (int ii = 0; ii < 4; ++ii) {
        int gi = qt * 64 + ty * 4 + ii;
        float* Cp = ctx + ((size_t)b * Sc + gi) * Dc + h * HS + tx * 4;
        *(float4*)Cp = make_float4(acc[ii][0], acc[ii][1], acc[ii][2], acc[ii][3]);
    }
}

// ----------------------------------------------------------------------------
// Launch
// ----------------------------------------------------------------------------
extern "C" void kernel_launch(void* const* d_in, const int* in_sizes, int n_in,
                              void* d_out, int out_size)
{
    const float* x     = (const float*)d_in[0];
    const float* w_in  = (const float*)d_in[1];
    const float* b_in  = (const float*)d_in[2];
    const float* w_out = (const float*)d_in[3];
    const float* b_out = (const float*)d_in[4];
    float* out = (float*)d_out;

    float *qkv, *ctx, *rmax, *rsum, *attn_scratch;
    cudaGetSymbolAddress((void**)&qkv,  g_qkv);
    cudaGetSymbolAddress((void**)&ctx,  g_ctx);
    cudaGetSymbolAddress((void**)&rmax, g_rowmax);
    cudaGetSymbolAddress((void**)&rsum, g_rowsum);
    cudaGetSymbolAddress((void**)&attn_scratch, g_attn);

    const size_t out_elems  = (size_t)Bc * Sc * Dc;              // 4,194,304
    const size_t attn_elems = (size_t)Bc * Hc * Sc * Sc;         // 134,217,728
    float* attn = ((size_t)out_size >= out_elems + attn_elems) ? (out + out_elems)
                                                               : attn_scratch;

    // 1) QKV projection: (4096 x 3072) = x (4096x1024) @ in_proj_w^T + b
    dim3 g1((3 * Dc) / 128, Mrows / 128);
    sgemm_bias_kernel<<<g1, 256>>>(x, w_in, b_in, qkv, Mrows, 3 * Dc, Dc);

    // 2) Scores + online softmax stats
    dim3 g2(Sc / 64, Bc * Hc);
    attn_scores_kernel<<<g2, 256>>>(qkv, attn, rmax, rsum);

    // 3) Normalize (and zero masked triangle)
    unsigned nblk = (unsigned)(attn_elems / 4 / 256);
    softmax_norm_kernel<<<nblk, 256>>>(attn, rmax, rsum);

    // 4) PV
    attn_pv_kernel<<<g2, 256>>>(attn, qkv, ctx);

    // 5) Output projection
    dim3 g3(Dc / 128, Mrows / 128);
    sgemm_bias_kernel<<<g3, 256>>>(ctx, w_out, b_out, out, Mrows, Dc, Dc);
}

// round 3
// speedup vs baseline: 1.3794x; 1.3794x over previous
#include <cuda_runtime.h>
#include <cuda_bf16.h>
#include <math.h>
#include <stdint.h>

// Problem constants
constexpr int Bc = 2;
constexpr int Sc = 2048;
constexpr int Dc = 1024;
constexpr int Hc = 16;
constexpr int HS = 64;           // head size
constexpr int Mrows = Bc * Sc;   // 4096

// ----------------------------------------------------------------------------
// Scratch (static __device__ globals; allocation in kernel_launch is forbidden)
// ----------------------------------------------------------------------------
__device__ float g_qkv[(size_t)Mrows * 3 * Dc];             // (B,S,3D)
__device__ float g_ctx[(size_t)Mrows * Dc];                 // (B,S,D)
__device__ float g_rowmax[(size_t)Bc * Hc * Sc];
__device__ float g_rowsum[(size_t)Bc * Hc * Sc];
__device__ float g_attn[(size_t)Bc * Hc * Sc * Sc];         // fallback if attn_w not in d_out

// bf16 hi/lo splits for tensor-core GEMMs
__device__ __nv_bfloat16 g_xh[(size_t)Mrows * Dc];
__device__ __nv_bfloat16 g_xl[(size_t)Mrows * Dc];
__device__ __nv_bfloat16 g_wih[(size_t)3 * Dc * Dc];
__device__ __nv_bfloat16 g_wil[(size_t)3 * Dc * Dc];
__device__ __nv_bfloat16 g_ch[(size_t)Mrows * Dc];
__device__ __nv_bfloat16 g_cl[(size_t)Mrows * Dc];
__device__ __nv_bfloat16 g_woh[(size_t)Dc * Dc];
__device__ __nv_bfloat16 g_wol[(size_t)Dc * Dc];

// ----------------------------------------------------------------------------
// Helpers
// ----------------------------------------------------------------------------
__device__ __forceinline__ uint32_t smem_u32(const void* p) {
    uint32_t a;
    asm("{ .reg .u64 t; cvta.to.shared.u64 t, %1; cvt.u32.u64 %0, t; }" : "=r"(a) : "l"(p));
    return a;
}
__device__ __forceinline__ uint32_t lds32(uint32_t a) {
    uint32_t v;
    asm volatile("ld.shared.b32 %0, [%1];" : "=r"(v) : "r"(a));
    return v;
}
#define CP_ASYNC16(dst, src) \
    asm volatile("cp.async.cg.shared.global [%0], [%1], 16;" :: "r"(dst), "l"(src) : "memory")
#define CP_COMMIT() asm volatile("cp.async.commit_group;" ::: "memory")
#define CP_WAIT(n)  asm volatile("cp.async.wait_group %0;" :: "n"(n) : "memory")

__device__ __forceinline__ void mma16816(float* c, const uint32_t* a, const uint32_t* b) {
    asm volatile(
        "mma.sync.aligned.m16n8k16.row.col.f32.bf16.bf16.f32 "
        "{%0,%1,%2,%3}, {%4,%5,%6,%7}, {%8,%9}, {%0,%1,%2,%3};"
        : "+f"(c[0]), "+f"(c[1]), "+f"(c[2]), "+f"(c[3])
        : "r"(a[0]), "r"(a[1]), "r"(a[2]), "r"(a[3]), "r"(b[0]), "r"(b[1]));
}

// ----------------------------------------------------------------------------
// fp32 -> (bf16 hi, bf16 lo) split (n multiple of 4)
// ----------------------------------------------------------------------------
__global__ __launch_bounds__(256) void split_bf16_kernel(
    const float4* __restrict__ src, __nv_bfloat162* __restrict__ hi,
    __nv_bfloat162* __restrict__ lo, int n4)
{
    int i = blockIdx.x * blockDim.x + threadIdx.x;
    if (i >= n4) return;
    float4 v = src[i];
    float vv[4] = {v.x, v.y, v.z, v.w};
    __nv_bfloat16 h[4], l[4];
#pragma unroll
    for (int k = 0; k < 4; ++k) {
        h[k] = __float2bfloat16(vv[k]);
        l[k] = __float2bfloat16(vv[k] - __bfloat162float(h[k]));
    }
    __nv_bfloat162 h0, h1, l0, l1;
    h0.x = h[0]; h0.y = h[1]; h1.x = h[2]; h1.y = h[3];
    l0.x = l[0]; l0.y = l[1]; l1.x = l[2]; l1.y = l[3];
    hi[i * 2 + 0] = h0; hi[i * 2 + 1] = h1;
    lo[i * 2 + 0] = l0; lo[i * 2 + 1] = l1;
}

// ----------------------------------------------------------------------------
// HMMA bf16x3 GEMM: C(MxN) = A(MxK) @ W(NxK)^T + bias
// 128x128 CTA tile, 8 warps (warp tile 32x64), K-chunk 32, cp.async double buf.
// Smem tiles padded to 40 elements per row (80B stride -> conflict-free frags).
// ----------------------------------------------------------------------------
constexpr int HG_LDS  = 40;                       // smem row stride (elements)
constexpr int HG_TILE = 128 * HG_LDS * 2;         // 10240 B per operand tile
constexpr int HG_STAGE = 4 * HG_TILE;             // Ah, Al, Wh, Wl
constexpr int HG_SMEM  = 2 * HG_STAGE;            // 81920 B

__global__ __launch_bounds__(256) void hmma_gemm_bias(
    const __nv_bfloat16* __restrict__ Ah, const __nv_bfloat16* __restrict__ Al,
    const __nv_bfloat16* __restrict__ Wh, const __nv_bfloat16* __restrict__ Wl,
    const float* __restrict__ bias, float* __restrict__ C,
    int M, int N, int K)
{
    extern __shared__ char smem[];
    const uint32_t sb = smem_u32(smem);

    const int tid  = threadIdx.x;
    const int wid  = tid >> 5;
    const int lane = tid & 31;
    const int lr   = lane >> 2;      // 0..7
    const int lc   = lane & 3;       // 0..3
    const int row0 = blockIdx.y * 128;
    const int col0 = blockIdx.x * 128;
    const int m0   = (wid & 3) * 32;   // warp M offset within tile
    const int n0   = (wid >> 2) * 64;  // warp N offset within tile

    const __nv_bfloat16* srcs[4] = {Ah, Al, Wh, Wl};

    auto load_stage = [&](int kc, uint32_t stage) {
#pragma unroll
        for (int i = 0; i < 8; ++i) {
            int idx = i * 256 + tid;        // 0..2047
            int t   = idx >> 9;             // operand 0..3
            int w   = idx & 511;
            int r   = w >> 2;               // row 0..127
            int c16 = w & 3;                // 16B chunk 0..3
            int base_rc = (t < 2) ? row0 : col0;
            const void* g = (const void*)(srcs[t] + (size_t)(base_rc + r) * K + kc * 32 + c16 * 8);
            uint32_t d = stage + (uint32_t)(t * HG_TILE) + (uint32_t)(r * 80 + c16 * 16);
            CP_ASYNC16(d, g);
        }
    };

    float acc[2][8][4];
#pragma unroll
    for (int mt = 0; mt < 2; ++mt)
#pragma unroll
        for (int nt = 0; nt < 8; ++nt)
#pragma unroll
            for (int q = 0; q < 4; ++q) acc[mt][nt][q] = 0.f;

    const int NC = K >> 5;   // chunks of 32

    load_stage(0, sb);
    CP_COMMIT();

    for (int c = 0; c < NC; ++c) {
        const uint32_t cur = sb + (uint32_t)((c & 1) * HG_STAGE);
        if (c + 1 < NC) {
            load_stage(c + 1, sb + (uint32_t)(((c + 1) & 1) * HG_STAGE));
            CP_COMMIT();
            CP_WAIT(1);
        } else {
            CP_WAIT(0);
        }
        __syncthreads();

        const uint32_t aH = cur;
        const uint32_t aL = cur + HG_TILE;
        const uint32_t wH = cur + 2 * HG_TILE;
        const uint32_t wL = cur + 3 * HG_TILE;

#pragma unroll
        for (int ks = 0; ks < 2; ++ks) {
            const uint32_t ko = (uint32_t)(ks * 32 + lc * 4);  // byte offset of k pair

            uint32_t ah[2][4], al[2][4];
#pragma unroll
            for (int mt = 0; mt < 2; ++mt) {
                uint32_t base = (uint32_t)((m0 + mt * 16 + lr) * 80) + ko;
                ah[mt][0] = lds32(aH + base);
                ah[mt][1] = lds32(aH + base + 8 * 80);
                ah[mt][2] = lds32(aH + base + 16);
                ah[mt][3] = lds32(aH + base + 8 * 80 + 16);
                al[mt][0] = lds32(aL + base);
                al[mt][1] = lds32(aL + base + 8 * 80);
                al[mt][2] = lds32(aL + base + 16);
                al[mt][3] = lds32(aL + base + 8 * 80 + 16);
            }
            uint32_t bh[8][2], bl[8][2];
#pragma unroll
            for (int nt = 0; nt < 8; ++nt) {
                uint32_t base = (uint32_t)((n0 + nt * 8 + lr) * 80) + ko;
                bh[nt][0] = lds32(wH + base);
                bh[nt][1] = lds32(wH + base + 16);
                bl[nt][0] = lds32(wL + base);
                bl[nt][1] = lds32(wL + base + 16);
            }
#pragma unroll
            for (int mt = 0; mt < 2; ++mt)
#pragma unroll
                for (int nt = 0; nt < 8; ++nt) {
                    mma16816(acc[mt][nt], ah[mt], bh[nt]);
                    mma16816(acc[mt][nt], ah[mt], bl[nt]);
                    mma16816(acc[mt][nt], al[mt], bh[nt]);
                }
        }
        __syncthreads();
    }

    // Epilogue: register fragments -> global, + bias
#pragma unroll
    for (int mt = 0; mt < 2; ++mt) {
#pragma unroll
        for (int nt = 0; nt < 8; ++nt) {
            int row = row0 + m0 + mt * 16 + lr;
            int col = col0 + n0 + nt * 8 + lc * 2;
            float b0 = __ldg(&bias[col]);
            float b1 = __ldg(&bias[col + 1]);
            float2 v0 = make_float2(acc[mt][nt][0] + b0, acc[mt][nt][1] + b1);
            float2 v1 = make_float2(acc[mt][nt][2] + b0, acc[mt][nt][3] + b1);
            *(float2*)(C + (size_t)row * N + col)       = v0;
            *(float2*)(C + (size_t)(row + 8) * N + col) = v1;
        }
    }
}

// ----------------------------------------------------------------------------
// Attention kernels (unchanged — proven correct)
// ----------------------------------------------------------------------------
__global__ __launch_bounds__(256) void attn_scores_kernel(
    const float* __restrict__ qkv, float* __restrict__ attn,
    float* __restrict__ rowmax, float* __restrict__ rowsum)
{
    __shared__ float QT[64][64];
    __shared__ float KT[64][64];

    const int qt = blockIdx.x;
    const int bh = blockIdx.y;
    const int b  = bh >> 4;
    const int h  = bh & 15;
    const float scale = 0.125f;

    const float* Qb = qkv + (size_t)b * Sc * (3 * Dc) + h * HS;
    const float* Kb = Qb + Dc;
    float* attn_bh = attn + (size_t)bh * Sc * Sc;

    const int tid = threadIdx.x;
    const int ty  = tid >> 4;
    const int tx  = tid & 15;

#pragma unroll
    for (int it = 0; it < 4; ++it) {
        int idx = tid + 256 * it;
        int r = idx >> 4;
        int c = (idx & 15) * 4;
        float4 v = *(const float4*)(Qb + (size_t)(qt * 64 + r) * (3 * Dc) + c);
        QT[c + 0][r] = v.x * scale; QT[c + 1][r] = v.y * scale;
        QT[c + 2][r] = v.z * scale; QT[c + 3][r] = v.w * scale;
    }

    float m[4], s[4];
#pragma unroll
    for (int i = 0; i < 4; ++i) { m[i] = -INFINITY; s[i] = 0.f; }

    for (int kt = 0; kt <= qt; ++kt) {
        __syncthreads();
#pragma unroll
        for (int it = 0; it < 4; ++it) {
            int idx = tid + 256 * it;
            int r = idx >> 4;
            int c = (idx & 15) * 4;
            float4 v = *(const float4*)(Kb + (size_t)(kt * 64 + r) * (3 * Dc) + c);
            KT[c + 0][r] = v.x; KT[c + 1][r] = v.y;
            KT[c + 2][r] = v.z; KT[c + 3][r] = v.w;
        }
        __syncthreads();

        float acc[4][4];
#pragma unroll
        for (int i = 0; i < 4; ++i)
#pragma unroll
            for (int j = 0; j < 4; ++j) acc[i][j] = 0.f;

#pragma unroll
        for (int k = 0; k < 64; ++k) {
            float4 aq = *(const float4*)&QT[k][ty * 4];
            float4 bk = *(const float4*)&KT[k][tx * 4];
            float a[4] = {aq.x, aq.y, aq.z, aq.w};
            float bb[4] = {bk.x, bk.y, bk.z, bk.w};
#pragma unroll
            for (int i = 0; i < 4; ++i)
#pragma unroll
                for (int j = 0; j < 4; ++j) acc[i][j] += a[i] * bb[j];
        }

        if (kt == qt) {
#pragma unroll
            for (int ii = 0; ii < 4; ++ii) {
                int gi = ty * 4 + ii;
#pragma unroll
                for (int jj = 0; jj < 4; ++jj) {
                    int gj = tx * 4 + jj;
                    if (gj > gi) acc[ii][jj] = -INFINITY;
                }
            }
        }

#pragma unroll
        for (int ii = 0; ii < 4; ++ii) {
            float tmax = fmaxf(fmaxf(acc[ii][0], acc[ii][1]),
                               fmaxf(acc[ii][2], acc[ii][3]));
            float nm = fmaxf(m[ii], tmax);
            if (nm != -INFINITY) {
                float add = __expf(acc[ii][0] - nm) + __expf(acc[ii][1] - nm) +
                            __expf(acc[ii][2] - nm) + __expf(acc[ii][3] - nm);
                s[ii] = s[ii] * __expf(m[ii] - nm) + add;
                m[ii] = nm;
            }
            int gi = qt * 64 + ty * 4 + ii;
            float4 st = make_float4(acc[ii][0], acc[ii][1], acc[ii][2], acc[ii][3]);
            *(float4*)(attn_bh + (size_t)gi * Sc + kt * 64 + tx * 4) = st;
        }
    }

#pragma unroll
    for (int ii = 0; ii < 4; ++ii) {
        float mm = m[ii], ss = s[ii];
#pragma unroll
        for (int off = 8; off > 0; off >>= 1) {
            float mo = __shfl_xor_sync(0xffffffffu, mm, off);
            float so = __shfl_xor_sync(0xffffffffu, ss, off);
            float M2 = fmaxf(mm, mo);
            ss = (M2 == -INFINITY) ? 0.f
                                   : (ss * __expf(mm - M2) + so * __expf(mo - M2));
            mm = M2;
        }
        if (tx == 0) {
            int gi = qt * 64 + ty * 4 + ii;
            rowmax[(size_t)bh * Sc + gi] = mm;
            rowsum[(size_t)bh * Sc + gi] = ss;
        }
    }
}

__global__ __launch_bounds__(256) void softmax_norm_kernel(
    float* __restrict__ attn, const float* __restrict__ rowmax,
    const float* __restrict__ rowsum)
{
    size_t i4 = (size_t)blockIdx.x * blockDim.x + threadIdx.x;
    size_t base = i4 * 4;
    int j = (int)(base & (size_t)(Sc - 1));
    size_t row = base >> 11;
    int i = (int)(row & (size_t)(Sc - 1));

    float4* p = (float4*)attn + i4;
    float4 v = *p;
    float mrow = rowmax[row];
    float inv  = 1.0f / rowsum[row];
    float4 o;
    o.x = (j + 0 > i) ? 0.f : __expf(v.x - mrow) * inv;
    o.y = (j + 1 > i) ? 0.f : __expf(v.y - mrow) * inv;
    o.z = (j + 2 > i) ? 0.f : __expf(v.z - mrow) * inv;
    o.w = (j + 3 > i) ? 0.f : __expf(v.w - mrow) * inv;
    *p = o;
}

__global__ __launch_bounds__(256) void attn_pv_kernel(
    const float* __restrict__ attn, const float* __restrict__ qkv,
    float* __restrict__ ctx)
{
    __shared__ float AT[64][64];
    __shared__ float Vs[64][64];

    const int qt = blockIdx.x;
    const int bh = blockIdx.y;
    const int b  = bh >> 4;
    const int h  = bh & 15;

    const float* Ab = attn + (size_t)bh * Sc * Sc;
    const float* Vb = qkv + (size_t)b * Sc * (3 * Dc) + 2 * Dc + h * HS;

    const int tid = threadIdx.x;
    const int ty  = tid >> 4;
    const int tx  = tid & 15;

    float acc[4][4];
#pragma unroll
    for (int i = 0; i < 4; ++i)
#pragma unroll
        for (int j = 0; j < 4; ++j) acc[i][j] = 0.f;

    for (int kt = 0; kt <= qt; ++kt) {
        __syncthreads();
#pragma unroll
        for (int it = 0; it < 4; ++it) {
            int idx = tid + 256 * it;
            int r = idx >> 4;
            int c = (idx & 15) * 4;
            float4 a = *(const float4*)(Ab + (size_t)(qt * 64 + r) * Sc + kt * 64 + c);
            AT[c + 0][r] = a.x; AT[c + 1][r] = a.y;
            AT[c + 2][r] = a.z; AT[c + 3][r] = a.w;
            float4 v = *(const float4*)(Vb + (size_t)(kt * 64 + r) * (3 * Dc) + c);
            *(float4*)&Vs[r][c] = v;
        }
        __syncthreads();
#pragma unroll
        for (int k = 0; k < 64; ++k) {
            float4 aa = *(const float4*)&AT[k][ty * 4];
            float4 vv = *(const float4*)&Vs[k][tx * 4];
            float a[4] = {aa.x, aa.y, aa.z, aa.w};
            float v[4] = {vv.x, vv.y, vv.z, vv.w};
#pragma unroll
            for (int i = 0; i < 4; ++i)
#pragma unroll
                for (int j = 0; j < 4; ++j) acc[i][j] += a[i] * v[j];
        }
    }

#pragma unroll
    for (int ii = 0; ii < 4; ++ii) {
        int gi = qt * 64 + ty * 4 + ii;
        float* Cp = ctx + ((size_t)b * Sc + gi) * Dc + h * HS + tx * 4;
        *(float4*)Cp = make_float4(acc[ii][0], acc[ii][1], acc[ii][2], acc[ii][3]);
    }
}

// ----------------------------------------------------------------------------
// Launch
// ----------------------------------------------------------------------------
extern "C" void kernel_launch(void* const* d_in, const int* in_sizes, int n_in,
                              void* d_out, int out_size)
{
    const float* x     = (const float*)d_in[0];
    const float* w_in  = (const float*)d_in[1];
    const float* b_in  = (const float*)d_in[2];
    const float* w_out = (const float*)d_in[3];
    const float* b_out = (const float*)d_in[4];
    float* out = (float*)d_out;

    float *qkv, *ctx, *rmax, *rsum, *attn_scratch;
    cudaGetSymbolAddress((void**)&qkv,  g_qkv);
    cudaGetSymbolAddress((void**)&ctx,  g_ctx);
    cudaGetSymbolAddress((void**)&rmax, g_rowmax);
    cudaGetSymbolAddress((void**)&rsum, g_rowsum);
    cudaGetSymbolAddress((void**)&attn_scratch, g_attn);

    __nv_bfloat16 *xh, *xl, *wih, *wil, *ch, *cl, *woh, *wol;
    cudaGetSymbolAddress((void**)&xh,  g_xh);
    cudaGetSymbolAddress((void**)&xl,  g_xl);
    cudaGetSymbolAddress((void**)&wih, g_wih);
    cudaGetSymbolAddress((void**)&wil, g_wil);
    cudaGetSymbolAddress((void**)&ch,  g_ch);
    cudaGetSymbolAddress((void**)&cl,  g_cl);
    cudaGetSymbolAddress((void**)&woh, g_woh);
    cudaGetSymbolAddress((void**)&wol, g_wol);

    const size_t out_elems  = (size_t)Bc * Sc * Dc;
    const size_t attn_elems = (size_t)Bc * Hc * Sc * Sc;
    float* attn = ((size_t)out_size >= out_elems + attn_elems) ? (out + out_elems)
                                                               : attn_scratch;

    cudaFuncSetAttribute(hmma_gemm_bias, cudaFuncAttributeMaxDynamicSharedMemorySize,
                         HG_SMEM);

    // Split inputs into bf16 hi/lo
    {
        int n4 = (Mrows * Dc) / 4;
        split_bf16_kernel<<<(n4 + 255) / 256, 256>>>((const float4*)x,
            (__nv_bfloat162*)xh, (__nv_bfloat162*)xl, n4);
        n4 = (3 * Dc * Dc) / 4;
        split_bf16_kernel<<<(n4 + 255) / 256, 256>>>((const float4*)w_in,
            (__nv_bfloat162*)wih, (__nv_bfloat162*)wil, n4);
        n4 = (Dc * Dc) / 4;
        split_bf16_kernel<<<(n4 + 255) / 256, 256>>>((const float4*)w_out,
            (__nv_bfloat162*)woh, (__nv_bfloat162*)wol, n4);
    }

    // 1) QKV projection (HMMA bf16x3)
    {
        dim3 g((3 * Dc) / 128, Mrows / 128);
        hmma_gemm_bias<<<g, 256, HG_SMEM>>>(xh, xl, wih, wil, b_in, qkv,
                                            Mrows, 3 * Dc, Dc);
    }

    // 2) Scores + online softmax stats
    dim3 g2(Sc / 64, Bc * Hc);
    attn_scores_kernel<<<g2, 256>>>(qkv, attn, rmax, rsum);

    // 3) Normalize (and zero masked triangle)
    unsigned nblk = (unsigned)(attn_elems / 4 / 256);
    softmax_norm_kernel<<<nblk, 256>>>(attn, rmax, rsum);

    // 4) PV
    attn_pv_kernel<<<g2, 256>>>(attn, qkv, ctx);

    // 5) Output projection (HMMA bf16x3)
    {
        int n4 = (Mrows * Dc) / 4;
        split_bf16_kernel<<<(n4 + 255) / 256, 256>>>((const float4*)ctx,
            (__nv_bfloat162*)ch, (__nv_bfloat162*)cl, n4);
        dim3 g(Dc / 128, Mrows / 128);
        hmma_gemm_bias<<<g, 256, HG_SMEM>>>(ch, cl, woh, wol, b_out, out,
                                            Mrows, Dc, Dc);
    }
}

// round 4
// speedup vs baseline: 2.5492x; 1.8480x over previous
#include <cuda_runtime.h>
#include <cuda_bf16.h>
#include <math.h>
#include <stdint.h>

// Problem constants
constexpr int Bc = 2;
constexpr int Sc = 2048;
constexpr int Dc = 1024;
constexpr int Hc = 16;
constexpr int HS = 64;
constexpr int Mrows = Bc * Sc;   // 4096

// ----------------------------------------------------------------------------
// Scratch (device globals; no allocation allowed)
// ----------------------------------------------------------------------------
__device__ float g_qkv[(size_t)Mrows * 3 * Dc];
__device__ float g_ctx[(size_t)Mrows * Dc];
__device__ float g_rowmax[(size_t)Bc * Hc * Sc];
__device__ float g_rowsum[(size_t)Bc * Hc * Sc];
__device__ float g_attn[(size_t)Bc * Hc * Sc * Sc];

__device__ __nv_bfloat16 g_xh[(size_t)Mrows * Dc];
__device__ __nv_bfloat16 g_xl[(size_t)Mrows * Dc];
__device__ __nv_bfloat16 g_wih[(size_t)3 * Dc * Dc];
__device__ __nv_bfloat16 g_wil[(size_t)3 * Dc * Dc];
__device__ __nv_bfloat16 g_ch[(size_t)Mrows * Dc];
__device__ __nv_bfloat16 g_cl[(size_t)Mrows * Dc];
__device__ __nv_bfloat16 g_woh[(size_t)Dc * Dc];
__device__ __nv_bfloat16 g_wol[(size_t)Dc * Dc];

// qkv split + transposed V + prob hi/lo
__device__ __nv_bfloat16 g_qkvh[(size_t)Mrows * 3 * Dc];
__device__ __nv_bfloat16 g_qkvl[(size_t)Mrows * 3 * Dc];
__device__ __nv_bfloat16 g_vth[(size_t)Bc * Hc * HS * Sc];
__device__ __nv_bfloat16 g_vtl[(size_t)Bc * Hc * HS * Sc];
__device__ __nv_bfloat16 g_ph[(size_t)Bc * Hc * Sc * Sc];
__device__ __nv_bfloat16 g_pl[(size_t)Bc * Hc * Sc * Sc];

// ----------------------------------------------------------------------------
// Helpers
// ----------------------------------------------------------------------------
__device__ __forceinline__ uint32_t smem_u32(const void* p) {
    uint32_t a;
    asm("{ .reg .u64 t; cvta.to.shared.u64 t, %1; cvt.u32.u64 %0, t; }" : "=r"(a) : "l"(p));
    return a;
}
__device__ __forceinline__ uint32_t lds32(uint32_t a) {
    uint32_t v;
    asm volatile("ld.shared.b32 %0, [%1];" : "=r"(v) : "r"(a));
    return v;
}
#define CP_ASYNC16(dst, src) \
    asm volatile("cp.async.cg.shared.global [%0], [%1], 16;" :: "r"(dst), "l"(src) : "memory")
#define CP_COMMIT() asm volatile("cp.async.commit_group;" ::: "memory")
#define CP_WAIT(n)  asm volatile("cp.async.wait_group %0;" :: "n"(n) : "memory")

__device__ __forceinline__ void mma16816(float* c, const uint32_t* a, const uint32_t* b) {
    asm volatile(
        "mma.sync.aligned.m16n8k16.row.col.f32.bf16.bf16.f32 "
        "{%0,%1,%2,%3}, {%4,%5,%6,%7}, {%8,%9}, {%0,%1,%2,%3};"
        : "+f"(c[0]), "+f"(c[1]), "+f"(c[2]), "+f"(c[3])
        : "r"(a[0]), "r"(a[1]), "r"(a[2]), "r"(a[3]), "r"(b[0]), "r"(b[1]));
}

// ----------------------------------------------------------------------------
// fp32 -> bf16 hi/lo split
// ----------------------------------------------------------------------------
__global__ __launch_bounds__(256) void split_bf16_kernel(
    const float4* __restrict__ src, __nv_bfloat162* __restrict__ hi,
    __nv_bfloat162* __restrict__ lo, int n4)
{
    int i = blockIdx.x * blockDim.x + threadIdx.x;
    if (i >= n4) return;
    float4 v = src[i];
    float vv[4] = {v.x, v.y, v.z, v.w};
    __nv_bfloat16 h[4], l[4];
#pragma unroll
    for (int k = 0; k < 4; ++k) {
        h[k] = __float2bfloat16(vv[k]);
        l[k] = __float2bfloat16(vv[k] - __bfloat162float(h[k]));
    }
    __nv_bfloat162 h0, h1, l0, l1;
    h0.x = h[0]; h0.y = h[1]; h1.x = h[2]; h1.y = h[3];
    l0.x = l[0]; l0.y = l[1]; l1.x = l[2]; l1.y = l[3];
    hi[i * 2 + 0] = h0; hi[i * 2 + 1] = h1;
    lo[i * 2 + 0] = l0; lo[i * 2 + 1] = l1;
}

// ----------------------------------------------------------------------------
// V transpose: qkv V region -> Vt[bh][hs][seq] bf16 hi/lo
// grid (Sc/64, Bc*Hc), block 256
// ----------------------------------------------------------------------------
__global__ __launch_bounds__(256) void vt_transpose_kernel(
    const float* __restrict__ qkv, __nv_bfloat16* __restrict__ vth,
    __nv_bfloat16* __restrict__ vtl)
{
    __shared__ float ts[64][65];
    const int s0 = blockIdx.x * 64;
    const int bh = blockIdx.y;
    const int b  = bh >> 4;
    const int h  = bh & 15;
    const int tid = threadIdx.x;

    const float* Vb = qkv + (size_t)b * Sc * 3072 + 2048 + h * 64;
#pragma unroll
    for (int i = 0; i < 4; ++i) {
        int idx = i * 256 + tid;        // 0..1023
        int r = idx >> 4;
        int c4 = idx & 15;
        float4 v = *(const float4*)(Vb + (size_t)(s0 + r) * 3072 + c4 * 4);
        ts[r][c4 * 4 + 0] = v.x; ts[r][c4 * 4 + 1] = v.y;
        ts[r][c4 * 4 + 2] = v.z; ts[r][c4 * 4 + 3] = v.w;
    }
    __syncthreads();
#pragma unroll
    for (int i = 0; i < 4; ++i) {
        int idx = i * 256 + tid;        // 0..1023
        int e  = idx >> 4;
        int sp = idx & 15;              // 4 seq each
        float f[4];
#pragma unroll
        for (int k = 0; k < 4; ++k) f[k] = ts[sp * 4 + k][e];
        __nv_bfloat16 hh[4], ll[4];
#pragma unroll
        for (int k = 0; k < 4; ++k) {
            hh[k] = __float2bfloat16(f[k]);
            ll[k] = __float2bfloat16(f[k] - __bfloat162float(hh[k]));
        }
        size_t off = (size_t)bh * HS * Sc + (size_t)e * Sc + s0 + sp * 4;
        __nv_bfloat162 p0, p1;
        p0.x = hh[0]; p0.y = hh[1]; p1.x = hh[2]; p1.y = hh[3];
        *(__nv_bfloat162*)(vth + off)     = p0;
        *(__nv_bfloat162*)(vth + off + 2) = p1;
        p0.x = ll[0]; p0.y = ll[1]; p1.x = ll[2]; p1.y = ll[3];
        *(__nv_bfloat162*)(vtl + off)     = p0;
        *(__nv_bfloat162*)(vtl + off + 2) = p1;
    }
}

// ----------------------------------------------------------------------------
// HMMA bf16x3 GEMM: C = A(MxK) @ W(NxK)^T + bias. 128x128 tile, 8 warps.
// ----------------------------------------------------------------------------
constexpr int HG_TILE = 128 * 40 * 2;             // 10240 B per operand tile
constexpr int HG_STAGE = 4 * HG_TILE;
constexpr int HG_SMEM  = 2 * HG_STAGE;            // 81920 B

__global__ __launch_bounds__(256, 2) void hmma_gemm_bias(
    const __nv_bfloat16* __restrict__ Ah, const __nv_bfloat16* __restrict__ Al,
    const __nv_bfloat16* __restrict__ Wh, const __nv_bfloat16* __restrict__ Wl,
    const float* __restrict__ bias, float* __restrict__ C,
    int M, int N, int K)
{
    extern __shared__ char smem[];
    const uint32_t sb = smem_u32(smem);

    const int tid  = threadIdx.x;
    const int wid  = tid >> 5;
    const int lane = tid & 31;
    const int lr   = lane >> 2;
    const int lc   = lane & 3;
    const int row0 = blockIdx.y * 128;
    const int col0 = blockIdx.x * 128;
    const int m0   = (wid & 3) * 32;
    const int n0   = (wid >> 2) * 64;

    const __nv_bfloat16* srcs[4] = {Ah, Al, Wh, Wl};

    auto load_stage = [&](int kc, uint32_t stage) {
#pragma unroll
        for (int i = 0; i < 8; ++i) {
            int idx = i * 256 + tid;
            int t   = idx >> 9;
            int w   = idx & 511;
            int r   = w >> 2;
            int c16 = w & 3;
            int base_rc = (t < 2) ? row0 : col0;
            const void* g = (const void*)(srcs[t] + (size_t)(base_rc + r) * K + kc * 32 + c16 * 8);
            uint32_t d = stage + (uint32_t)(t * HG_TILE) + (uint32_t)(r * 80 + c16 * 16);
            CP_ASYNC16(d, g);
        }
    };

    float acc[2][8][4];
#pragma unroll
    for (int mt = 0; mt < 2; ++mt)
#pragma unroll
        for (int nt = 0; nt < 8; ++nt)
#pragma unroll
            for (int q = 0; q < 4; ++q) acc[mt][nt][q] = 0.f;

    const int NC = K >> 5;
    load_stage(0, sb);
    CP_COMMIT();

    for (int c = 0; c < NC; ++c) {
        const uint32_t cur = sb + (uint32_t)((c & 1) * HG_STAGE);
        if (c + 1 < NC) {
            load_stage(c + 1, sb + (uint32_t)(((c + 1) & 1) * HG_STAGE));
            CP_COMMIT();
            CP_WAIT(1);
        } else {
            CP_WAIT(0);
        }
        __syncthreads();

        const uint32_t aH = cur;
        const uint32_t aL = cur + HG_TILE;
        const uint32_t wH = cur + 2 * HG_TILE;
        const uint32_t wL = cur + 3 * HG_TILE;

#pragma unroll
        for (int ks = 0; ks < 2; ++ks) {
            const uint32_t ko = (uint32_t)(ks * 32 + lc * 4);
            uint32_t ah[2][4], al[2][4];
#pragma unroll
            for (int mt = 0; mt < 2; ++mt) {
                uint32_t base = (uint32_t)((m0 + mt * 16 + lr) * 80) + ko;
                ah[mt][0] = lds32(aH + base);
                ah[mt][1] = lds32(aH + base + 8 * 80);
                ah[mt][2] = lds32(aH + base + 16);
                ah[mt][3] = lds32(aH + base + 8 * 80 + 16);
                al[mt][0] = lds32(aL + base);
                al[mt][1] = lds32(aL + base + 8 * 80);
                al[mt][2] = lds32(aL + base + 16);
                al[mt][3] = lds32(aL + base + 8 * 80 + 16);
            }
#pragma unroll
            for (int ng = 0; ng < 2; ++ng) {
                uint32_t bh4[4][2], bl4[4][2];
#pragma unroll
                for (int nt = 0; nt < 4; ++nt) {
                    uint32_t base = (uint32_t)((n0 + (ng * 4 + nt) * 8 + lr) * 80) + ko;
                    bh4[nt][0] = lds32(wH + base);
                    bh4[nt][1] = lds32(wH + base + 16);
                    bl4[nt][0] = lds32(wL + base);
                    bl4[nt][1] = lds32(wL + base + 16);
                }
#pragma unroll
                for (int mt = 0; mt < 2; ++mt)
#pragma unroll
                    for (int nt = 0; nt < 4; ++nt) {
                        mma16816(acc[mt][ng * 4 + nt], ah[mt], bh4[nt]);
                        mma16816(acc[mt][ng * 4 + nt], ah[mt], bl4[nt]);
                        mma16816(acc[mt][ng * 4 + nt], al[mt], bh4[nt]);
                    }
            }
        }
        __syncthreads();
    }

#pragma unroll
    for (int mt = 0; mt < 2; ++mt) {
#pragma unroll
        for (int nt = 0; nt < 8; ++nt) {
            int row = row0 + m0 + mt * 16 + lr;
            int col = col0 + n0 + nt * 8 + lc * 2;
            float b0 = __ldg(&bias[col]);
            float b1 = __ldg(&bias[col + 1]);
            float2 v0 = make_float2(acc[mt][nt][0] + b0, acc[mt][nt][1] + b1);
            float2 v1 = make_float2(acc[mt][nt][2] + b0, acc[mt][nt][3] + b1);
            *(float2*)(C + (size_t)row * N + col)       = v0;
            *(float2*)(C + (size_t)(row + 8) * N + col) = v1;
        }
    }
}

// ----------------------------------------------------------------------------
// HMMA scores: per (qt 128 rows, bh). Raw scaled scores -> attn; (m,s) stats.
// Warp tile: 16 rows x 128 cols. smem rows padded to 144B.
// ----------------------------------------------------------------------------
constexpr int SC_QL   = 18432;            // 128*144
constexpr int SC_K    = 36864;
constexpr int SC_KST  = 36864;            // per stage (Kh+Kl)
constexpr int SC_SMEM = SC_K + 2 * SC_KST;   // 110592

__global__ __launch_bounds__(256, 2) void attn_scores_hmma(
    const __nv_bfloat16* __restrict__ qkvh, const __nv_bfloat16* __restrict__ qkvl,
    float* __restrict__ attn, float* __restrict__ rowmax, float* __restrict__ rowsum)
{
    extern __shared__ char smem[];
    const uint32_t sb = smem_u32(smem);
    const int qt = blockIdx.x;
    const int bh = blockIdx.y;
    const int b  = bh >> 4;
    const int h  = bh & 15;
    const int tid = threadIdx.x, w = tid >> 5, lane = tid & 31;
    const int lr = lane >> 2, lc = lane & 3;

    const __nv_bfloat16* Qh = qkvh + (size_t)b * Sc * 3072 + (size_t)qt * 128 * 3072 + h * 64;
    const __nv_bfloat16* Ql = qkvl + (size_t)b * Sc * 3072 + (size_t)qt * 128 * 3072 + h * 64;
    const __nv_bfloat16* Kh = qkvh + (size_t)b * Sc * 3072 + 1024 + h * 64;
    const __nv_bfloat16* Kl = qkvl + (size_t)b * Sc * 3072 + 1024 + h * 64;
    float* attn_bh = attn + (size_t)bh * Sc * Sc;

    // load Q (hi+lo)
#pragma unroll
    for (int i = 0; i < 8; ++i) {
        int idx = i * 256 + tid;
        int op = idx >> 10;
        int ww = idx & 1023;
        int r = ww >> 3, c = ww & 7;
        const void* g = (const void*)((op ? Ql : Qh) + (size_t)r * 3072 + c * 8);
        CP_ASYNC16(sb + (uint32_t)(op * SC_QL) + (uint32_t)(r * 144 + c * 16), g);
    }
    auto load_k = [&](int kt, int st) {
        uint32_t base = sb + SC_K + (uint32_t)(st * SC_KST);
#pragma unroll
        for (int i = 0; i < 8; ++i) {
            int idx = i * 256 + tid;
            int op = idx >> 10;
            int ww = idx & 1023;
            int r = ww >> 3, c = ww & 7;
            const void* g = (const void*)((op ? Kl : Kh) + (size_t)(kt * 128 + r) * 3072 + c * 8);
            CP_ASYNC16(base + (uint32_t)(op * 18432) + (uint32_t)(r * 144 + c * 16), g);
        }
    };
    load_k(0, 0);
    CP_COMMIT();

    float m_run[2] = {-INFINITY, -INFINITY};
    float s_run[2] = {0.f, 0.f};

    const uint32_t qbh = sb + (uint32_t)((w * 16 + lr) * 144);
    const uint32_t qbl = qbh + SC_QL;

    for (int kt = 0; kt <= qt; ++kt) {
        if (kt < qt) {
            load_k(kt + 1, (kt + 1) & 1);
            CP_COMMIT();
            CP_WAIT(1);
        } else {
            CP_WAIT(0);
        }
        __syncthreads();

        const uint32_t kbh = sb + SC_K + (uint32_t)((kt & 1) * SC_KST);
        const uint32_t kbl = kbh + 18432;

        float acc[16][4];
#pragma unroll
        for (int nt = 0; nt < 16; ++nt)
#pragma unroll
            for (int q = 0; q < 4; ++q) acc[nt][q] = 0.f;

#pragma unroll
        for (int ks = 0; ks < 4; ++ks) {
            const uint32_t ko = (uint32_t)(ks * 32 + lc * 4);
            uint32_t ah[4], al[4];
            ah[0] = lds32(qbh + ko);            ah[1] = lds32(qbh + 8 * 144 + ko);
            ah[2] = lds32(qbh + ko + 16);       ah[3] = lds32(qbh + 8 * 144 + ko + 16);
            al[0] = lds32(qbl + ko);            al[1] = lds32(qbl + 8 * 144 + ko);
            al[2] = lds32(qbl + ko + 16);       al[3] = lds32(qbl + 8 * 144 + ko + 16);
#pragma unroll
            for (int nt = 0; nt < 16; ++nt) {
                uint32_t kr = (uint32_t)((nt * 8 + lr) * 144) + ko;
                uint32_t bhf[2] = {lds32(kbh + kr), lds32(kbh + kr + 16)};
                uint32_t blf[2] = {lds32(kbl + kr), lds32(kbl + kr + 16)};
                mma16816(acc[nt], ah, bhf);
                mma16816(acc[nt], ah, blf);
                mma16816(acc[nt], al, bhf);
            }
        }

        // scale, mask, store, stats
        const bool diag = (kt == qt);
        const int r0 = w * 16 + lr;
#pragma unroll
        for (int nt = 0; nt < 16; ++nt) {
#pragma unroll
            for (int q = 0; q < 4; ++q) {
                float v = acc[nt][q] * 0.125f;
                if (diag) {
                    int rl = r0 + ((q >= 2) ? 8 : 0);
                    int cl = nt * 8 + lc * 2 + (q & 1);
                    if (cl > rl) v = -INFINITY;
                }
                acc[nt][q] = v;
            }
            float* p0 = attn_bh + (size_t)(qt * 128 + r0) * Sc + kt * 128 + nt * 8 + lc * 2;
            *(float2*)p0 = make_float2(acc[nt][0], acc[nt][1]);
            *(float2*)(p0 + 8 * Sc) = make_float2(acc[nt][2], acc[nt][3]);
        }
#pragma unroll
        for (int r = 0; r < 2; ++r) {
            float tm = -INFINITY;
#pragma unroll
            for (int nt = 0; nt < 16; ++nt)
                tm = fmaxf(tm, fmaxf(acc[nt][r * 2], acc[nt][r * 2 + 1]));
            tm = fmaxf(tm, __shfl_xor_sync(0xffffffffu, tm, 1));
            tm = fmaxf(tm, __shfl_xor_sync(0xffffffffu, tm, 2));
            float nm = fmaxf(m_run[r], tm);
            float sl = 0.f;
#pragma unroll
            for (int nt = 0; nt < 16; ++nt)
                sl += __expf(acc[nt][r * 2] - nm) + __expf(acc[nt][r * 2 + 1] - nm);
            sl += __shfl_xor_sync(0xffffffffu, sl, 1);
            sl += __shfl_xor_sync(0xffffffffu, sl, 2);
            s_run[r] = s_run[r] * __expf(m_run[r] - nm) + sl;
            m_run[r] = nm;
        }
        __syncthreads();
    }

    if (lc == 0) {
        int gi0 = qt * 128 + w * 16 + lr;
        rowmax[(size_t)bh * Sc + gi0]     = m_run[0];
        rowsum[(size_t)bh * Sc + gi0]     = s_run[0];
        rowmax[(size_t)bh * Sc + gi0 + 8] = m_run[1];
        rowsum[(size_t)bh * Sc + gi0 + 8] = s_run[1];
    }
}

// ----------------------------------------------------------------------------
// Normalize + emit bf16 hi/lo probs (causal tiles only)
// ----------------------------------------------------------------------------
__global__ __launch_bounds__(256) void softmax_norm_kernel(
    float* __restrict__ attn, const float* __restrict__ rowmax,
    const float* __restrict__ rowsum,
    __nv_bfloat162* __restrict__ ph, __nv_bfloat162* __restrict__ pl)
{
    size_t i4 = (size_t)blockIdx.x * blockDim.x + threadIdx.x;
    size_t base = i4 * 4;
    int j = (int)(base & (size_t)(Sc - 1));
    size_t row = base >> 11;
    int i = (int)(row & (size_t)(Sc - 1));

    float4* p = (float4*)attn + i4;
    if (j > i) {
        *p = make_float4(0.f, 0.f, 0.f, 0.f);
        if ((j >> 7) == (i >> 7)) {
            __nv_bfloat162 z;
            z.x = __float2bfloat16(0.f); z.y = z.x;
            ph[i4 * 2] = z; ph[i4 * 2 + 1] = z;
            pl[i4 * 2] = z; pl[i4 * 2 + 1] = z;
        }
        return;
    }
    float4 v = *p;
    float mrow = rowmax[row];
    float inv  = 1.0f / rowsum[row];
    float4 o;
    o.x = (j + 0 > i) ? 0.f : __expf(v.x - mrow) * inv;
    o.y = (j + 1 > i) ? 0.f : __expf(v.y - mrow) * inv;
    o.z = (j + 2 > i) ? 0.f : __expf(v.z - mrow) * inv;
    o.w = (j + 3 > i) ? 0.f : __expf(v.w - mrow) * inv;
    *p = o;

    float ov[4] = {o.x, o.y, o.z, o.w};
    __nv_bfloat16 hh[4], ll[4];
#pragma unroll
    for (int k = 0; k < 4; ++k) {
        hh[k] = __float2bfloat16(ov[k]);
        ll[k] = __float2bfloat16(ov[k] - __bfloat162float(hh[k]));
    }
    __nv_bfloat162 a, bb;
    a.x = hh[0]; a.y = hh[1]; bb.x = hh[2]; bb.y = hh[3];
    ph[i4 * 2] = a; ph[i4 * 2 + 1] = bb;
    a.x = ll[0]; a.y = ll[1]; bb.x = ll[2]; bb.y = ll[3];
    pl[i4 * 2] = a; pl[i4 * 2 + 1] = bb;
}

// ----------------------------------------------------------------------------
// HMMA PV: ctx[128 x 64] = P[128 x S_causal] @ V[S x 64], bf16x3.
// smem rows padded to 272B. Double-buffered stages of (Ph, Pl, Vh, Vl).
// ----------------------------------------------------------------------------
constexpr int PV_P    = 34816;            // 128*272
constexpr int PV_V    = 17408;            // 64*272
constexpr int PV_STAGE = 2 * PV_P + 2 * PV_V;   // 104448
constexpr int PV_SMEM  = 2 * PV_STAGE;          // 208896

__global__ __launch_bounds__(256, 1) void attn_pv_hmma(
    const __nv_bfloat16* __restrict__ ph, const __nv_bfloat16* __restrict__ pl,
    const __nv_bfloat16* __restrict__ vth, const __nv_bfloat16* __restrict__ vtl,
    float* __restrict__ ctx)
{
    extern __shared__ char smem[];
    const uint32_t sb = smem_u32(smem);
    const int qt = blockIdx.x;
    const int bh = blockIdx.y;
    const int b  = bh >> 4;
    const int h  = bh & 15;
    const int tid = threadIdx.x, w = tid >> 5, lane = tid & 31;
    const int lr = lane >> 2, lc = lane & 3;

    const __nv_bfloat16* Pb[2] = {ph + (size_t)bh * Sc * Sc + (size_t)qt * 128 * Sc,
                                  pl + (size_t)bh * Sc * Sc + (size_t)qt * 128 * Sc};
    const __nv_bfloat16* Vb[2] = {vth + (size_t)bh * HS * Sc,
                                  vtl + (size_t)bh * HS * Sc};

    auto load_stage = [&](int kt, int st) {
        uint32_t base = sb + (uint32_t)(st * PV_STAGE);
#pragma unroll
        for (int i = 0; i < 24; ++i) {
            int idx = i * 256 + tid;          // 0..6143
            if (idx < 4096) {                  // P tiles
                int op = idx >> 11;
                int ww = idx & 2047;
                int r = ww >> 4, c = ww & 15;
                const void* g = (const void*)(Pb[op] + (size_t)r * Sc + kt * 128 + c * 8);
                CP_ASYNC16(base + (uint32_t)(op * PV_P) + (uint32_t)(r * 272 + c * 16), g);
            } else {                           // V tiles
                int idx2 = idx - 4096;
                int op = idx2 >> 10;
                int ww = idx2 & 1023;
                int r = ww >> 4, c = ww & 15;
                const void* g = (const void*)(Vb[op] + (size_t)r * Sc + kt * 128 + c * 8);
                CP_ASYNC16(base + (uint32_t)(2 * PV_P + op * PV_V) + (uint32_t)(r * 272 + c * 16), g);
            }
        }
    };

    float acc[8][4];
#pragma unroll
    for (int nt = 0; nt < 8; ++nt)
#pragma unroll
        for (int q = 0; q < 4; ++q) acc[nt][q] = 0.f;

    load_stage(0, 0);
    CP_COMMIT();

    const uint32_t prow = (uint32_t)((w * 16 + lr) * 272);

    for (int kt = 0; kt <= qt; ++kt) {
        if (kt < qt) {
            load_stage(kt + 1, (kt + 1) & 1);
            CP_COMMIT();
            CP_WAIT(1);
        } else {
            CP_WAIT(0);
        }
        __syncthreads();

        const uint32_t st = sb + (uint32_t)((kt & 1) * PV_STAGE);
        const uint32_t pH = st, pL = st + PV_P;
        const uint32_t vH = st + 2 * PV_P, vL = vH + PV_V;

#pragma unroll
        for (int ks = 0; ks < 8; ++ks) {
            const uint32_t ko = (uint32_t)(ks * 32 + lc * 4);
            uint32_t ah[4], al[4];
            ah[0] = lds32(pH + prow + ko);       ah[1] = lds32(pH + prow + 8 * 272 + ko);
            ah[2] = lds32(pH + prow + ko + 16);  ah[3] = lds32(pH + prow + 8 * 272 + ko + 16);
            al[0] = lds32(pL + prow + ko);       al[1] = lds32(pL + prow + 8 * 272 + ko);
            al[2] = lds32(pL + prow + ko + 16);  al[3] = lds32(pL + prow + 8 * 272 + ko + 16);
#pragma unroll
            for (int nt = 0; nt < 8; ++nt) {
                uint32_t vr = (uint32_t)((nt * 8 + lr) * 272) + ko;
                uint32_t bhf[2] = {lds32(vH + vr), lds32(vH + vr + 16)};
                uint32_t blf[2] = {lds32(vL + vr), lds32(vL + vr + 16)};
                mma16816(acc[nt], ah, bhf);
                mma16816(acc[nt], ah, blf);
                mma16816(acc[nt], al, bhf);
            }
        }
        __syncthreads();
    }

#pragma unroll
    for (int nt = 0; nt < 8; ++nt) {
        int gi = qt * 128 + w * 16 + lr;
        float* Cp = ctx + ((size_t)b * Sc + gi) * Dc + h * HS + nt * 8 + lc * 2;
        *(float2*)Cp = make_float2(acc[nt][0], acc[nt][1]);
        *(float2*)(Cp + 8 * Dc) = make_float2(acc[nt][2], acc[nt][3]);
    }
}

// ----------------------------------------------------------------------------
// Launch
// ----------------------------------------------------------------------------
extern "C" void kernel_launch(void* const* d_in, const int* in_sizes, int n_in,
                              void* d_out, int out_size)
{
    const float* x     = (const float*)d_in[0];
    const float* w_in  = (const float*)d_in[1];
    const float* b_in  = (const float*)d_in[2];
    const float* w_out = (const float*)d_in[3];
    const float* b_out = (const float*)d_in[4];
    float* out = (float*)d_out;

    float *qkv, *ctx, *rmax, *rsum, *attn_scratch;
    cudaGetSymbolAddress((void**)&qkv,  g_qkv);
    cudaGetSymbolAddress((void**)&ctx,  g_ctx);
    cudaGetSymbolAddress((void**)&rmax, g_rowmax);
    cudaGetSymbolAddress((void**)&rsum, g_rowsum);
    cudaGetSymbolAddress((void**)&attn_scratch, g_attn);

    __nv_bfloat16 *xh, *xl, *wih, *wil, *ch, *cl, *woh, *wol;
    __nv_bfloat16 *qkvh, *qkvl, *vth, *vtl, *ph, *pl;
    cudaGetSymbolAddress((void**)&xh,  g_xh);
    cudaGetSymbolAddress((void**)&xl,  g_xl);
    cudaGetSymbolAddress((void**)&wih, g_wih);
    cudaGetSymbolAddress((void**)&wil, g_wil);
    cudaGetSymbolAddress((void**)&ch,  g_ch);
    cudaGetSymbolAddress((void**)&cl,  g_cl);
    cudaGetSymbolAddress((void**)&woh, g_woh);
    cudaGetSymbolAddress((void**)&wol, g_wol);
    cudaGetSymbolAddress((void**)&qkvh, g_qkvh);
    cudaGetSymbolAddress((void**)&qkvl, g_qkvl);
    cudaGetSymbolAddress((void**)&vth, g_vth);
    cudaGetSymbolAddress((void**)&vtl, g_vtl);
    cudaGetSymbolAddress((void**)&ph,  g_ph);
    cudaGetSymbolAddress((void**)&pl,  g_pl);

    const size_t out_elems  = (size_t)Bc * Sc * Dc;
    const size_t attn_elems = (size_t)Bc * Hc * Sc * Sc;
    float* attn = ((size_t)out_size >= out_elems + attn_elems) ? (out + out_elems)
                                                               : attn_scratch;

    cudaFuncSetAttribute(hmma_gemm_bias, cudaFuncAttributeMaxDynamicSharedMemorySize, HG_SMEM);
    cudaFuncSetAttribute(attn_scores_hmma, cudaFuncAttributeMaxDynamicSharedMemorySize, SC_SMEM);
    cudaFuncSetAttribute(attn_pv_hmma, cudaFuncAttributeMaxDynamicSharedMemorySize, PV_SMEM);

    // Splits of inputs
    {
        int n4 = (Mrows * Dc) / 4;
        split_bf16_kernel<<<(n4 + 255) / 256, 256>>>((const float4*)x,
            (__nv_bfloat162*)xh, (__nv_bfloat162*)xl, n4);
        n4 = (3 * Dc * Dc) / 4;
        split_bf16_kernel<<<(n4 + 255) / 256, 256>>>((const float4*)w_in,
            (__nv_bfloat162*)wih, (__nv_bfloat162*)wil, n4);
        n4 = (Dc * Dc) / 4;
        split_bf16_kernel<<<(n4 + 255) / 256, 256>>>((const float4*)w_out,
            (__nv_bfloat162*)woh, (__nv_bfloat162*)wol, n4);
    }

    // 1) QKV projection
    {
        dim3 g((3 * Dc) / 128, Mrows / 128);
        hmma_gemm_bias<<<g, 256, HG_SMEM>>>(xh, xl, wih, wil, b_in, qkv, Mrows, 3 * Dc, Dc);
    }

    // 2) Split qkv; transpose V
    {
        int n4 = (Mrows * 3 * Dc) / 4;
        split_bf16_kernel<<<(n4 + 255) / 256, 256>>>((const float4*)qkv,
            (__nv_bfloat162*)qkvh, (__nv_bfloat162*)qkvl, n4);
        dim3 gt(Sc / 64, Bc * Hc);
        vt_transpose_kernel<<<gt, 256>>>(qkv, vth, vtl);
    }

    // 3) Scores (HMMA) + stats
    dim3 g2(Sc / 128, Bc * Hc);
    attn_scores_hmma<<<g2, 256, SC_SMEM>>>(qkvh, qkvl, attn, rmax, rsum);

    // 4) Normalize + emit prob hi/lo
    unsigned nblk = (unsigned)(attn_elems / 4 / 256);
    softmax_norm_kernel<<<nblk, 256>>>(attn, rmax, rsum,
                                       (__nv_bfloat162*)ph, (__nv_bfloat162*)pl);

    // 5) PV (HMMA)
    attn_pv_hmma<<<g2, 256, PV_SMEM>>>(ph, pl, vth, vtl, ctx);

    // 6) Output projection
    {
        int n4 = (Mrows * Dc) / 4;
        split_bf16_kernel<<<(n4 + 255) / 256, 256>>>((const float4*)ctx,
            (__nv_bfloat162*)ch, (__nv_bfloat162*)cl, n4);
        dim3 g(Dc / 128, Mrows / 128);
        hmma_gemm_bias<<<g, 256, HG_SMEM>>>(ch, cl, woh, wol, b_out, out, Mrows, Dc, Dc);
    }
}